// round 1
// baseline (speedup 1.0000x reference)
#include <cuda_runtime.h>
#include <math.h>

// ---------------------------------------------------------------------------
// Aligner: out = softmax((ix@W^T+b) @ (io@W^T+b)^T) @ io
// B=8, L=2048, D=1024, fp32.
// Round 0: pure-fp32 tiled SGEMM pipeline (precision-safe baseline).
// ---------------------------------------------------------------------------

#define BATCH 8
#define LSEQ  2048
#define DIM   1024

#define BM 128
#define BN 128
#define BK 16
#define TM 8
#define TN 8
// 256 threads: 16x16 thread grid, each thread owns an 8x8 micro-tile.

// Scratch (allocation-free rule: __device__ globals)
__device__ float g_ex[(size_t)BATCH * LSEQ * DIM];   // 64 MB
__device__ float g_eo[(size_t)BATCH * LSEQ * DIM];   // 64 MB
__device__ float g_s [(size_t)BATCH * LSEQ * LSEQ];  // 128 MB

// ---------------------------------------------------------------------------
// C = A * B^T (+bias), A:[M,K] row-major, B:[N,K] row-major, C:[M,N] row-major
// All of M,N divisible by 128, K divisible by 16. Batched via blockIdx.z.
// ---------------------------------------------------------------------------
__global__ __launch_bounds__(256, 2)
void gemm_nt(const float* __restrict__ A, const float* __restrict__ B,
             float* __restrict__ C, const float* __restrict__ bias,
             int M, int N, int K,
             long long sA, long long sB, long long sC)
{
    __shared__ float As[BK][BM];
    __shared__ float Bs[BK][BN];

    A += (long long)blockIdx.z * sA;
    B += (long long)blockIdx.z * sB;
    C += (long long)blockIdx.z * sC;

    const int tid = threadIdx.x;
    const int tx  = tid & 15;      // 0..15 -> N direction
    const int ty  = tid >> 4;      // 0..15 -> M direction
    const int rowC = blockIdx.y * BM;
    const int colC = blockIdx.x * BN;

    const float* Aptr = A + (long long)rowC * K;
    const float* Bptr = B + (long long)colC * K;

    float acc[TM][TN];
    #pragma unroll
    for (int i = 0; i < TM; ++i)
        #pragma unroll
        for (int j = 0; j < TN; ++j) acc[i][j] = 0.f;

    for (int k0 = 0; k0 < K; k0 += BK) {
        // 128x16 tile = 512 float4; 256 threads x 2 float4.
        #pragma unroll
        for (int jj = 0; jj < 2; ++jj) {
            int idx = tid * 2 + jj;
            int r   = idx >> 2;           // row within tile (0..127)
            int c4  = (idx & 3) * 4;      // starting k within tile (0,4,8,12)
            float4 va = *(const float4*)(Aptr + (long long)r * K + k0 + c4);
            As[c4+0][r] = va.x; As[c4+1][r] = va.y;
            As[c4+2][r] = va.z; As[c4+3][r] = va.w;
            float4 vb = *(const float4*)(Bptr + (long long)r * K + k0 + c4);
            Bs[c4+0][r] = vb.x; Bs[c4+1][r] = vb.y;
            Bs[c4+2][r] = vb.z; Bs[c4+3][r] = vb.w;
        }
        __syncthreads();

        #pragma unroll
        for (int k = 0; k < BK; ++k) {
            float a[TM], b[TN];
            float4 a0 = *(const float4*)&As[k][ty * TM];
            float4 a1 = *(const float4*)&As[k][ty * TM + 4];
            a[0]=a0.x; a[1]=a0.y; a[2]=a0.z; a[3]=a0.w;
            a[4]=a1.x; a[5]=a1.y; a[6]=a1.z; a[7]=a1.w;
            float4 b0 = *(const float4*)&Bs[k][tx * TN];
            float4 b1 = *(const float4*)&Bs[k][tx * TN + 4];
            b[0]=b0.x; b[1]=b0.y; b[2]=b0.z; b[3]=b0.w;
            b[4]=b1.x; b[5]=b1.y; b[6]=b1.z; b[7]=b1.w;
            #pragma unroll
            for (int i = 0; i < TM; ++i)
                #pragma unroll
                for (int j = 0; j < TN; ++j)
                    acc[i][j] = fmaf(a[i], b[j], acc[i][j]);
        }
        __syncthreads();
    }

    #pragma unroll
    for (int i = 0; i < TM; ++i) {
        int m = rowC + ty * TM + i;
        #pragma unroll
        for (int j = 0; j < TN; j += 4) {
            int n = colC + tx * TN + j;
            float4 v;
            v.x = acc[i][j+0]; v.y = acc[i][j+1];
            v.z = acc[i][j+2]; v.w = acc[i][j+3];
            if (bias) {
                v.x += bias[n+0]; v.y += bias[n+1];
                v.z += bias[n+2]; v.w += bias[n+3];
            }
            *(float4*)(C + (long long)m * N + n) = v;
        }
    }
}

// ---------------------------------------------------------------------------
// C = A * B, A:[M,K] row-major, B:[K,N] row-major, C:[M,N] row-major.
// ---------------------------------------------------------------------------
__global__ __launch_bounds__(256, 2)
void gemm_nn(const float* __restrict__ A, const float* __restrict__ B,
             float* __restrict__ C,
             int M, int N, int K,
             long long sA, long long sB, long long sC)
{
    __shared__ float As[BK][BM];
    __shared__ float Bs[BK][BN];

    A += (long long)blockIdx.z * sA;
    B += (long long)blockIdx.z * sB;
    C += (long long)blockIdx.z * sC;

    const int tid = threadIdx.x;
    const int tx  = tid & 15;
    const int ty  = tid >> 4;
    const int rowC = blockIdx.y * BM;
    const int colC = blockIdx.x * BN;

    const float* Aptr = A + (long long)rowC * K;

    float acc[TM][TN];
    #pragma unroll
    for (int i = 0; i < TM; ++i)
        #pragma unroll
        for (int j = 0; j < TN; ++j) acc[i][j] = 0.f;

    for (int k0 = 0; k0 < K; k0 += BK) {
        #pragma unroll
        for (int jj = 0; jj < 2; ++jj) {
            int idx = tid * 2 + jj;
            // A tile: 128 rows x 16 k
            int ra  = idx >> 2;
            int c4  = (idx & 3) * 4;
            float4 va = *(const float4*)(Aptr + (long long)ra * K + k0 + c4);
            As[c4+0][ra] = va.x; As[c4+1][ra] = va.y;
            As[c4+2][ra] = va.z; As[c4+3][ra] = va.w;
            // B tile: 16 k-rows x 128 n (direct copy, no transpose)
            int kb  = idx >> 5;            // 0..15
            int n4  = (idx & 31) * 4;      // 0..124
            float4 vb = *(const float4*)(B + (long long)(k0 + kb) * N + colC + n4);
            *(float4*)&Bs[kb][n4] = vb;
        }
        __syncthreads();

        #pragma unroll
        for (int k = 0; k < BK; ++k) {
            float a[TM], b[TN];
            float4 a0 = *(const float4*)&As[k][ty * TM];
            float4 a1 = *(const float4*)&As[k][ty * TM + 4];
            a[0]=a0.x; a[1]=a0.y; a[2]=a0.z; a[3]=a0.w;
            a[4]=a1.x; a[5]=a1.y; a[6]=a1.z; a[7]=a1.w;
            float4 b0 = *(const float4*)&Bs[k][tx * TN];
            float4 b1 = *(const float4*)&Bs[k][tx * TN + 4];
            b[0]=b0.x; b[1]=b0.y; b[2]=b0.z; b[3]=b0.w;
            b[4]=b1.x; b[5]=b1.y; b[6]=b1.z; b[7]=b1.w;
            #pragma unroll
            for (int i = 0; i < TM; ++i)
                #pragma unroll
                for (int j = 0; j < TN; ++j)
                    acc[i][j] = fmaf(a[i], b[j], acc[i][j]);
        }
        __syncthreads();
    }

    #pragma unroll
    for (int i = 0; i < TM; ++i) {
        int m = rowC + ty * TM + i;
        #pragma unroll
        for (int j = 0; j < TN; j += 4) {
            int n = colC + tx * TN + j;
            float4 v;
            v.x = acc[i][j+0]; v.y = acc[i][j+1];
            v.z = acc[i][j+2]; v.w = acc[i][j+3];
            *(float4*)(C + (long long)m * N + n) = v;
        }
    }
}

// ---------------------------------------------------------------------------
// In-place row softmax. One block (256 threads) per row of `cols` floats.
// ---------------------------------------------------------------------------
__global__ void softmax_rows(float* __restrict__ S, int cols)
{
    float* row = S + (long long)blockIdx.x * cols;
    const int tid = threadIdx.x;

    float lmax = -3.0e38f;
    for (int i = tid * 4; i < cols; i += 256 * 4) {
        float4 v = *(const float4*)(row + i);
        lmax = fmaxf(lmax, fmaxf(fmaxf(v.x, v.y), fmaxf(v.z, v.w)));
    }
    #pragma unroll
    for (int o = 16; o; o >>= 1)
        lmax = fmaxf(lmax, __shfl_xor_sync(0xFFFFFFFFu, lmax, o));

    __shared__ float sm[8];
    __shared__ float ss[8];
    if ((tid & 31) == 0) sm[tid >> 5] = lmax;
    __syncthreads();
    float rmax = fmaxf(fmaxf(fmaxf(sm[0], sm[1]), fmaxf(sm[2], sm[3])),
                       fmaxf(fmaxf(sm[4], sm[5]), fmaxf(sm[6], sm[7])));

    float lsum = 0.f;
    for (int i = tid * 4; i < cols; i += 256 * 4) {
        float4 v = *(const float4*)(row + i);
        v.x = expf(v.x - rmax);
        v.y = expf(v.y - rmax);
        v.z = expf(v.z - rmax);
        v.w = expf(v.w - rmax);
        *(float4*)(row + i) = v;
        lsum += v.x + v.y + v.z + v.w;
    }
    #pragma unroll
    for (int o = 16; o; o >>= 1)
        lsum += __shfl_xor_sync(0xFFFFFFFFu, lsum, o);
    if ((tid & 31) == 0) ss[tid >> 5] = lsum;
    __syncthreads();
    float inv = 1.f / (ss[0]+ss[1]+ss[2]+ss[3]+ss[4]+ss[5]+ss[6]+ss[7]);

    for (int i = tid * 4; i < cols; i += 256 * 4) {
        float4 v = *(const float4*)(row + i);
        v.x *= inv; v.y *= inv; v.z *= inv; v.w *= inv;
        *(float4*)(row + i) = v;
    }
}

// ---------------------------------------------------------------------------
extern "C" void kernel_launch(void* const* d_in, const int* in_sizes, int n_in,
                              void* d_out, int out_size)
{
    const float* ix = (const float*)d_in[0];
    const float* io = (const float*)d_in[1];
    const float* W  = (const float*)d_in[2];
    const float* bb = (const float*)d_in[3];
    float* out = (float*)d_out;

    float *ex, *eo, *s;
    cudaGetSymbolAddress((void**)&ex, g_ex);
    cudaGetSymbolAddress((void**)&eo, g_eo);
    cudaGetSymbolAddress((void**)&s,  g_s);

    dim3 blk(256);

    // 1) projections: E = X @ W^T + b  (M=16384, N=1024, K=1024)
    dim3 g1(DIM / BN, (BATCH * LSEQ) / BM, 1);
    gemm_nt<<<g1, blk>>>(ix, W, ex, bb, BATCH * LSEQ, DIM, DIM, 0, 0, 0);
    gemm_nt<<<g1, blk>>>(io, W, eo, bb, BATCH * LSEQ, DIM, DIM, 0, 0, 0);

    // 2) scores: S[b] = Ex[b] @ Eo[b]^T  (M=N=2048, K=1024, batched over B)
    dim3 g2(LSEQ / BN, LSEQ / BM, BATCH);
    gemm_nt<<<g2, blk>>>(ex, eo, s, nullptr, LSEQ, LSEQ, DIM,
                         (long long)LSEQ * DIM, (long long)LSEQ * DIM,
                         (long long)LSEQ * LSEQ);

    // 3) softmax over last dim, in place
    softmax_rows<<<BATCH * LSEQ, 256>>>(s, LSEQ);

    // 4) out[b] = P[b] @ io[b]  (M=2048, N=1024, K=2048, batched over B)
    dim3 g4(DIM / BN, LSEQ / BM, BATCH);
    gemm_nn<<<g4, blk>>>(s, io, out, LSEQ, DIM, LSEQ,
                         (long long)LSEQ * LSEQ, (long long)LSEQ * DIM,
                         (long long)LSEQ * DIM);
}

// round 3
// speedup vs baseline: 1.9717x; 1.9717x over previous
#include <cuda_runtime.h>
#include <cuda_bf16.h>
#include <cstdint>
#include <math.h>

// ============================================================================
// Aligner: out = softmax((ix@W^T+b) @ (io@W^T+b)^T) @ io
// B=8, L=2048, D=1024, fp32 in/out.
// Round 3: mma.sync (HMMA) bf16 tensor-core GEMMs with 2-term split precision
// (3 passes hi*hi + hi*lo + lo*hi into fp32 accumulators).
// (tcgen05 is unavailable: harness PTX target is sm_103 without the 'a'
//  feature set, so only portable PTX tensor-core instructions can be used.)
// ============================================================================

#define BATCH 8
#define LSEQ  2048
#define DIM   1024
#define MELEMS ((size_t)BATCH * LSEQ * DIM)    // 16,777,216
#define SELEMS ((size_t)BATCH * LSEQ * LSEQ)   // 33,554,432

// ---- scratch (__device__ globals per allocation rules) ----
__device__ __nv_bfloat16 g_ix_hi[MELEMS],  g_ix_lo[MELEMS];
__device__ __nv_bfloat16 g_io_hi[MELEMS],  g_io_lo[MELEMS];
__device__ __nv_bfloat16 g_ioT_hi[MELEMS], g_ioT_lo[MELEMS];
__device__ __nv_bfloat16 g_ex_hi[MELEMS],  g_ex_lo[MELEMS];
__device__ __nv_bfloat16 g_eo_hi[MELEMS],  g_eo_lo[MELEMS];
__device__ __nv_bfloat16 g_w_hi[DIM * DIM], g_w_lo[DIM * DIM];
__device__ float         g_s[SELEMS];
__device__ __nv_bfloat16 g_p_hi[SELEMS],   g_p_lo[SELEMS];

// ============================================================================
// PTX helpers (portable: cp.async / ldmatrix / mma.sync only)
// ============================================================================
__device__ __forceinline__ uint32_t smem_u32(const void* p) {
    uint32_t a;
    asm("{ .reg .u64 t; cvta.to.shared.u64 t, %1; cvt.u32.u64 %0, t; }"
        : "=r"(a) : "l"(p));
    return a;
}

#define CP_COMMIT() asm volatile("cp.async.commit_group;" ::: "memory")
#define CP_WAIT(N)  asm volatile("cp.async.wait_group %0;" :: "n"(N) : "memory")

__device__ __forceinline__ void cp16(uint32_t dst, const void* src) {
    asm volatile("cp.async.cg.shared.global [%0], [%1], 16;" :: "r"(dst), "l"(src));
}

__device__ __forceinline__ void ldsm4(uint32_t* r, uint32_t addr) {
    asm volatile("ldmatrix.sync.aligned.m8n8.x4.shared.b16 {%0,%1,%2,%3}, [%4];"
                 : "=r"(r[0]), "=r"(r[1]), "=r"(r[2]), "=r"(r[3]) : "r"(addr));
}

__device__ __forceinline__ void mma16816(float* d, const uint32_t* a,
                                         const uint32_t* b) {
    asm volatile(
        "mma.sync.aligned.m16n8k16.row.col.f32.bf16.bf16.f32 "
        "{%0,%1,%2,%3}, {%4,%5,%6,%7}, {%8,%9}, {%0,%1,%2,%3};"
        : "+f"(d[0]), "+f"(d[1]), "+f"(d[2]), "+f"(d[3])
        : "r"(a[0]), "r"(a[1]), "r"(a[2]), "r"(a[3]), "r"(b[0]), "r"(b[1]));
}

// tile layout: [128 rows][64 bytes], 16B chunks swizzled: chunk ^ ((row>>1)&3)
__device__ __forceinline__ uint32_t tile_addr(uint32_t base, int row, int chunk) {
    return base + row * 64 + ((chunk ^ ((row >> 1) & 3)) << 4);
}

// ============================================================================
// Split / transpose / softmax helper kernels
// ============================================================================
__device__ __forceinline__ void split1(float v, __nv_bfloat16& h, __nv_bfloat16& l) {
    h = __float2bfloat16(v);
    l = __float2bfloat16(v - __bfloat162float(h));
}

__global__ void split_f32(const float* __restrict__ s,
                          __nv_bfloat16* __restrict__ hi,
                          __nv_bfloat16* __restrict__ lo, size_t n) {
    size_t i = ((size_t)blockIdx.x * blockDim.x + threadIdx.x) * 4;
    if (i >= n) return;
    float4 v = *(const float4*)(s + i);
    __nv_bfloat16 h0, h1, h2, h3, l0, l1, l2, l3;
    split1(v.x, h0, l0); split1(v.y, h1, l1);
    split1(v.z, h2, l2); split1(v.w, h3, l3);
    *(__nv_bfloat162*)(hi + i)     = __nv_bfloat162(h0, h1);
    *(__nv_bfloat162*)(hi + i + 2) = __nv_bfloat162(h2, h3);
    *(__nv_bfloat162*)(lo + i)     = __nv_bfloat162(l0, l1);
    *(__nv_bfloat162*)(lo + i + 2) = __nv_bfloat162(l2, l3);
}

// per-batch transpose [L, D] -> [D, L] with bf16 split outputs
__global__ void transpose_split(const float* __restrict__ src,
                                __nv_bfloat16* __restrict__ hiT,
                                __nv_bfloat16* __restrict__ loT) {
    __shared__ float t[32][33];
    int b = blockIdx.z;
    int l0 = blockIdx.x * 32, d0 = blockIdx.y * 32;
    const float* s = src + (size_t)b * LSEQ * DIM;
    #pragma unroll
    for (int i = 0; i < 32; i += 8)
        t[threadIdx.y + i][threadIdx.x] =
            s[(size_t)(l0 + threadIdx.y + i) * DIM + d0 + threadIdx.x];
    __syncthreads();
    size_t ob = (size_t)b * DIM * LSEQ;
    #pragma unroll
    for (int i = 0; i < 32; i += 8) {
        float v = t[threadIdx.x][threadIdx.y + i];
        __nv_bfloat16 h, l;
        split1(v, h, l);
        size_t o = ob + (size_t)(d0 + threadIdx.y + i) * LSEQ + l0 + threadIdx.x;
        hiT[o] = h;
        loT[o] = l;
    }
}

// row softmax; writes bf16 hi/lo probability split
__global__ void softmax_split(float* __restrict__ S,
                              __nv_bfloat16* __restrict__ phi,
                              __nv_bfloat16* __restrict__ plo, int cols) {
    float* row = S + (size_t)blockIdx.x * cols;
    __nv_bfloat16* hr = phi + (size_t)blockIdx.x * cols;
    __nv_bfloat16* lr = plo + (size_t)blockIdx.x * cols;
    const int tid = threadIdx.x;

    float lmax = -3.0e38f;
    for (int i = tid * 4; i < cols; i += 1024) {
        float4 v = *(const float4*)(row + i);
        lmax = fmaxf(lmax, fmaxf(fmaxf(v.x, v.y), fmaxf(v.z, v.w)));
    }
    #pragma unroll
    for (int o = 16; o; o >>= 1)
        lmax = fmaxf(lmax, __shfl_xor_sync(0xFFFFFFFFu, lmax, o));
    __shared__ float sm[8], ss[8];
    if ((tid & 31) == 0) sm[tid >> 5] = lmax;
    __syncthreads();
    float rmax = fmaxf(fmaxf(fmaxf(sm[0], sm[1]), fmaxf(sm[2], sm[3])),
                       fmaxf(fmaxf(sm[4], sm[5]), fmaxf(sm[6], sm[7])));

    float lsum = 0.f;
    for (int i = tid * 4; i < cols; i += 1024) {
        float4 v = *(const float4*)(row + i);
        v.x = expf(v.x - rmax); v.y = expf(v.y - rmax);
        v.z = expf(v.z - rmax); v.w = expf(v.w - rmax);
        *(float4*)(row + i) = v;
        lsum += v.x + v.y + v.z + v.w;
    }
    #pragma unroll
    for (int o = 16; o; o >>= 1)
        lsum += __shfl_xor_sync(0xFFFFFFFFu, lsum, o);
    if ((tid & 31) == 0) ss[tid >> 5] = lsum;
    __syncthreads();
    float inv = 1.f / (ss[0]+ss[1]+ss[2]+ss[3]+ss[4]+ss[5]+ss[6]+ss[7]);

    for (int i = tid * 4; i < cols; i += 1024) {
        float4 v = *(const float4*)(row + i);
        v.x *= inv; v.y *= inv; v.z *= inv; v.w *= inv;
        __nv_bfloat16 h0,h1,h2,h3,l0,l1,l2,l3;
        split1(v.x,h0,l0); split1(v.y,h1,l1); split1(v.z,h2,l2); split1(v.w,h3,l3);
        *(__nv_bfloat162*)(hr + i)     = __nv_bfloat162(h0, h1);
        *(__nv_bfloat162*)(hr + i + 2) = __nv_bfloat162(h2, h3);
        *(__nv_bfloat162*)(lr + i)     = __nv_bfloat162(l0, l1);
        *(__nv_bfloat162*)(lr + i + 2) = __nv_bfloat162(l2, l3);
    }
}

// ============================================================================
// Split-precision HMMA GEMM.
// C[m,n] = sum_k (Ahi+Alo)[m,k]*(Bhi+Blo)[n,k]  (lo*lo dropped)
// A,B: K-major bf16. Output fp32 (Cf) or bf16 split (Chi/Clo), optional bias.
// Grid: (N/128, M/128, batch), 256 threads (8 warps, 2x4, warp tile 64x32).
// smem: 2 stages x {Ahi,Alo,Bhi,Blo} x [128 x 32] bf16 (8KB each) = 64KB.
// ============================================================================
#define BKC 32
#define TILE_B 8192
#define STAGE_B (4 * TILE_B)

__global__ __launch_bounds__(256, 1)
void gemm_split(const __nv_bfloat16* __restrict__ Ahi, const __nv_bfloat16* __restrict__ Alo,
                const __nv_bfloat16* __restrict__ Bhi, const __nv_bfloat16* __restrict__ Blo,
                float* __restrict__ Cf,
                __nv_bfloat16* __restrict__ Chi, __nv_bfloat16* __restrict__ Clo,
                const float* __restrict__ bias,
                int K, int N,
                long long sA, long long sB, long long sC)
{
    extern __shared__ __align__(128) char smem[];
    const uint32_t sb = smem_u32(smem);

    const int tid  = threadIdx.x;
    const int wid  = tid >> 5;
    const int lane = tid & 31;
    const int wm   = wid >> 2;       // 0..1 (64 rows each)
    const int wn   = wid & 3;        // 0..3 (32 cols each)

    const long long bz = blockIdx.z;
    const long long m0 = (long long)blockIdx.y * 128;
    const long long n0 = (long long)blockIdx.x * 128;

    const __nv_bfloat16* srcs[4] = {
        Ahi + bz * sA + m0 * K, Alo + bz * sA + m0 * K,
        Bhi + bz * sB + n0 * K, Blo + bz * sB + n0 * K };

    // ---- cp.async one K-chunk (4 tiles of [128 x 32] bf16) ----
    auto load_chunk = [&](int stage, int k0) {
        const uint32_t base = sb + stage * STAGE_B;
        #pragma unroll
        for (int t = 0; t < 4; ++t) {
            #pragma unroll
            for (int j = 0; j < 2; ++j) {
                int idx = tid * 2 + j;        // 0..511
                int row = idx >> 2;
                int ch  = idx & 3;
                cp16(tile_addr(base + t * TILE_B, row, ch),
                     srcs[t] + (long long)row * K + k0 + ch * 8);
            }
        }
        CP_COMMIT();
    };

    float acc[4][4][4];
    #pragma unroll
    for (int i = 0; i < 4; ++i)
        #pragma unroll
        for (int j = 0; j < 4; ++j)
            #pragma unroll
            for (int e = 0; e < 4; ++e) acc[i][j][e] = 0.f;

    const int NC = K >> 5;
    load_chunk(0, 0);

    const int lrow = lane & 15;      // ldmatrix row within 16-row group
    const int lch  = lane >> 4;      // ldmatrix 16B column select (0/1)

    for (int c = 0; c < NC; ++c) {
        if (c + 1 < NC) { load_chunk((c + 1) & 1, (c + 1) * BKC); CP_WAIT(1); }
        else            { CP_WAIT(0); }
        __syncthreads();

        const uint32_t st  = sb + (c & 1) * STAGE_B;
        const uint32_t sAh = st;
        const uint32_t sAl = st + TILE_B;
        const uint32_t sBh = st + 2 * TILE_B;
        const uint32_t sBl = st + 3 * TILE_B;

        #pragma unroll
        for (int ks = 0; ks < 2; ++ks) {
            const int chunk = ks * 2 + lch;
            uint32_t ahi[4][4], alo[4][4];
            uint32_t bhi[4][2], blo[4][2];

            #pragma unroll
            for (int mi = 0; mi < 4; ++mi) {
                const int row = wm * 64 + mi * 16 + lrow;
                ldsm4(ahi[mi], tile_addr(sAh, row, chunk));
                ldsm4(alo[mi], tile_addr(sAl, row, chunk));
            }
            #pragma unroll
            for (int bi = 0; bi < 2; ++bi) {
                const int row = wn * 32 + bi * 16 + lrow;
                uint32_t t4[4];
                ldsm4(t4, tile_addr(sBh, row, chunk));
                bhi[bi*2][0] = t4[0]; bhi[bi*2][1]   = t4[2];
                bhi[bi*2+1][0] = t4[1]; bhi[bi*2+1][1] = t4[3];
                ldsm4(t4, tile_addr(sBl, row, chunk));
                blo[bi*2][0] = t4[0]; blo[bi*2][1]   = t4[2];
                blo[bi*2+1][0] = t4[1]; blo[bi*2+1][1] = t4[3];
            }

            #pragma unroll
            for (int mi = 0; mi < 4; ++mi)
                #pragma unroll
                for (int ni = 0; ni < 4; ++ni) {
                    mma16816(acc[mi][ni], ahi[mi], bhi[ni]);
                    mma16816(acc[mi][ni], ahi[mi], blo[ni]);
                    mma16816(acc[mi][ni], alo[mi], bhi[ni]);
                }
        }
        __syncthreads();
    }

    // ---- epilogue ----
    const int r1 = lane >> 2;
    const int c0 = (lane & 3) * 2;
    #pragma unroll
    for (int mi = 0; mi < 4; ++mi) {
        #pragma unroll
        for (int ni = 0; ni < 4; ++ni) {
            const long long gm = m0 + wm * 64 + mi * 16 + r1;
            const long long gn = n0 + wn * 32 + ni * 8 + c0;
            float v0 = acc[mi][ni][0], v1 = acc[mi][ni][1];
            float v2 = acc[mi][ni][2], v3 = acc[mi][ni][3];
            if (bias) {
                float b0 = bias[gn], b1 = bias[gn + 1];
                v0 += b0; v1 += b1; v2 += b0; v3 += b1;
            }
            if (Cf) {
                float* d0 = Cf + bz * sC + gm * N + gn;
                float* d1 = Cf + bz * sC + (gm + 8) * N + gn;
                d0[0] = v0; d0[1] = v1;
                d1[0] = v2; d1[1] = v3;
            } else {
                __nv_bfloat16 h0, h1, h2, h3, l0, l1, l2, l3;
                split1(v0, h0, l0); split1(v1, h1, l1);
                split1(v2, h2, l2); split1(v3, h3, l3);
                *(__nv_bfloat162*)(Chi + bz * sC + gm * N + gn)       = __nv_bfloat162(h0, h1);
                *(__nv_bfloat162*)(Clo + bz * sC + gm * N + gn)       = __nv_bfloat162(l0, l1);
                *(__nv_bfloat162*)(Chi + bz * sC + (gm + 8) * N + gn) = __nv_bfloat162(h2, h3);
                *(__nv_bfloat162*)(Clo + bz * sC + (gm + 8) * N + gn) = __nv_bfloat162(l2, l3);
            }
        }
    }
}

// ============================================================================
extern "C" void kernel_launch(void* const* d_in, const int* in_sizes, int n_in,
                              void* d_out, int out_size)
{
    const float* ix = (const float*)d_in[0];
    const float* io = (const float*)d_in[1];
    const float* W  = (const float*)d_in[2];
    const float* bb = (const float*)d_in[3];
    float* out = (float*)d_out;

    __nv_bfloat16 *ix_hi, *ix_lo, *io_hi, *io_lo, *ioT_hi, *ioT_lo;
    __nv_bfloat16 *ex_hi, *ex_lo, *eo_hi, *eo_lo, *w_hi, *w_lo, *p_hi, *p_lo;
    float* s;
    cudaGetSymbolAddress((void**)&ix_hi, g_ix_hi);
    cudaGetSymbolAddress((void**)&ix_lo, g_ix_lo);
    cudaGetSymbolAddress((void**)&io_hi, g_io_hi);
    cudaGetSymbolAddress((void**)&io_lo, g_io_lo);
    cudaGetSymbolAddress((void**)&ioT_hi, g_ioT_hi);
    cudaGetSymbolAddress((void**)&ioT_lo, g_ioT_lo);
    cudaGetSymbolAddress((void**)&ex_hi, g_ex_hi);
    cudaGetSymbolAddress((void**)&ex_lo, g_ex_lo);
    cudaGetSymbolAddress((void**)&eo_hi, g_eo_hi);
    cudaGetSymbolAddress((void**)&eo_lo, g_eo_lo);
    cudaGetSymbolAddress((void**)&w_hi, g_w_hi);
    cudaGetSymbolAddress((void**)&w_lo, g_w_lo);
    cudaGetSymbolAddress((void**)&p_hi, g_p_hi);
    cudaGetSymbolAddress((void**)&p_lo, g_p_lo);
    cudaGetSymbolAddress((void**)&s, g_s);

    static bool attr_set = false;
    const int smem_bytes = 2 * STAGE_B;  // 64 KB
    if (!attr_set) {
        cudaFuncSetAttribute(gemm_split,
                             cudaFuncAttributeMaxDynamicSharedMemorySize, smem_bytes);
        attr_set = true;
    }

    // 1) splits
    split_f32<<<(unsigned)(MELEMS / 4 / 256), 256>>>(ix, ix_hi, ix_lo, MELEMS);
    split_f32<<<(unsigned)(MELEMS / 4 / 256), 256>>>(io, io_hi, io_lo, MELEMS);
    split_f32<<<(DIM * DIM) / 4 / 256, 256>>>(W, w_hi, w_lo, (size_t)DIM * DIM);
    transpose_split<<<dim3(LSEQ / 32, DIM / 32, BATCH), dim3(32, 8)>>>(io, ioT_hi, ioT_lo);

    // 2) projections: E = X @ W^T + b -> bf16 split (M=16384, N=1024, K=1024)
    {
        dim3 g(DIM / 128, (BATCH * LSEQ) / 128, 1);
        gemm_split<<<g, 256, smem_bytes>>>(ix_hi, ix_lo, w_hi, w_lo,
                                           nullptr, ex_hi, ex_lo, bb,
                                           DIM, DIM, 0, 0, 0);
        gemm_split<<<g, 256, smem_bytes>>>(io_hi, io_lo, w_hi, w_lo,
                                           nullptr, eo_hi, eo_lo, bb,
                                           DIM, DIM, 0, 0, 0);
    }

    // 3) scores: S[b] = Ex[b] @ Eo[b]^T -> fp32 (M=N=2048, K=1024)
    {
        dim3 g(LSEQ / 128, LSEQ / 128, BATCH);
        gemm_split<<<g, 256, smem_bytes>>>(ex_hi, ex_lo, eo_hi, eo_lo,
                                           s, nullptr, nullptr, nullptr,
                                           DIM, LSEQ,
                                           (long long)LSEQ * DIM,
                                           (long long)LSEQ * DIM,
                                           (long long)LSEQ * LSEQ);
    }

    // 4) softmax -> P bf16 split
    softmax_split<<<BATCH * LSEQ, 256>>>(s, p_hi, p_lo, LSEQ);

    // 5) out[b] = P[b] @ ioT[b]^T -> fp32 d_out (M=2048, N=1024, K=2048)
    {
        dim3 g(DIM / 128, LSEQ / 128, BATCH);
        gemm_split<<<g, 256, smem_bytes>>>(p_hi, p_lo, ioT_hi, ioT_lo,
                                           out, nullptr, nullptr, nullptr,
                                           LSEQ, DIM,
                                           (long long)LSEQ * LSEQ,
                                           (long long)DIM * LSEQ,
                                           (long long)LSEQ * DIM);
    }
}